// round 4
// baseline (speedup 1.0000x reference)
#include <cuda_runtime.h>
#include <cuda_fp16.h>
#include <cstdint>

#define DIM 512
#define TMt 128
#define TNt 128
#define KC 64
#define NK 8
#define QPITCHF 68                  // floats per q row (64 + 4 pad)
#define BPITCHH 72                  // halves per S row (64 + 8 pad)
#define QBUF_F (128 * QPITCHF)      // 8704 floats
#define BBUF_H (128 * BPITCHH)      // 9216 halves
#define SMEM_BYTES (3 * QBUF_F * 4 + 3 * BBUF_H * 2)   // 159744

// S = A + A^T in fp16; 512 KB, L2-resident during GEMM
__device__ __half g_Sh[DIM * DIM];

__global__ void prep_S(const float* __restrict__ A) {
    int i = blockIdx.x * 256 + threadIdx.x;   // 262144 total
    int e = i >> 9, d = i & 511;
    g_Sh[i] = __float2half(A[i] + A[d * DIM + e]);
}

// ---------------- helpers ----------------
__device__ __forceinline__ uint32_t smem_u32(const void* p) {
    return (uint32_t)__cvta_generic_to_shared(p);
}
__device__ __forceinline__ void cpa16(uint32_t dst, const void* src) {
    asm volatile("cp.async.cg.shared.global [%0], [%1], 16;" :: "r"(dst), "l"(src) : "memory");
}
__device__ __forceinline__ void cp_commit() { asm volatile("cp.async.commit_group;" ::: "memory"); }
__device__ __forceinline__ void cp_wait2()  { asm volatile("cp.async.wait_group 2;" ::: "memory"); }

__device__ __forceinline__ uint32_t packh2(float x, float y) {
    __half2 h = __floats2half2_rn(x, y);          // lo = x, hi = y
    return *reinterpret_cast<uint32_t*>(&h);
}
__device__ __forceinline__ void mma16816(float* d, uint32_t a0, uint32_t a1, uint32_t a2,
                                         uint32_t a3, uint32_t b0, uint32_t b1) {
    asm volatile(
        "mma.sync.aligned.m16n8k16.row.col.f32.f16.f16.f32 "
        "{%0,%1,%2,%3}, {%4,%5,%6,%7}, {%8,%9}, {%0,%1,%2,%3};"
        : "+f"(d[0]), "+f"(d[1]), "+f"(d[2]), "+f"(d[3])
        : "r"(a0), "r"(a1), "r"(a2), "r"(a3), "r"(b0), "r"(b1));
}

// ---------------- main fused kernel ----------------
// out[:, 0:512]    = p + q @ S   (pterm[b][e] = sum_d q[b][d] * S[e][d], S symmetric)
// out[:, 512:1024] = q
__global__ void __launch_bounds__(256, 1)
gemm_fused(const float* __restrict__ pq, float* __restrict__ out) {
    extern __shared__ __align__(16) char smem_raw[];
    float* qsm = reinterpret_cast<float*>(smem_raw);                  // 3 stages
    __half* bsm = reinterpret_cast<__half*>(smem_raw + 3 * QBUF_F * 4);
    const uint32_t qsm_u = smem_u32(qsm);
    const uint32_t bsm_u = smem_u32(bsm);

    const int tid = threadIdx.x;
    const int wid = tid >> 5, lane = tid & 31;
    const int wm = wid & 3, wn = wid >> 2;        // warp grid 4(m) x 2(n); warp tile 32x64
    const int l4 = lane >> 2, lc = lane & 3;
    const int bx = blockIdx.x;
    const int m0 = (bx >> 2) * TMt;
    const int n0 = (bx & 3) * TNt;

    float d[2][8][4];
    #pragma unroll
    for (int i = 0; i < 2; i++)
        #pragma unroll
        for (int j = 0; j < 8; j++)
            #pragma unroll
            for (int k = 0; k < 4; k++) d[i][j][k] = 0.f;

    // issue cp.async for K-chunk kc into stage kc%3
    auto issue = [&](int kc) {
        const uint32_t qb = qsm_u + (kc % 3) * (QBUF_F * 4);
        const uint32_t bb = bsm_u + (kc % 3) * (BBUF_H * 2);
        const float* qs = pq + (size_t)m0 * 1024 + DIM + kc * KC;
        #pragma unroll
        for (int j = 0; j < 8; j++) {
            int i = tid + j * 256;                // 2048 x 16B
            int r = i >> 4, c = i & 15;
            cpa16(qb + (r * QPITCHF + c * 4) * 4, qs + (size_t)r * 1024 + c * 4);
        }
        const __half* ss = g_Sh + (size_t)n0 * DIM + kc * KC;
        #pragma unroll
        for (int j = 0; j < 4; j++) {
            int i = tid + j * 256;                // 1024 x 16B
            int r = i >> 3, c = i & 7;
            cpa16(bb + (r * BPITCHH + c * 8) * 2, ss + (size_t)r * DIM + c * 8);
        }
    };

    issue(0); cp_commit();
    issue(1); cp_commit();

    for (int kc = 0; kc < NK; kc++) {
        __syncthreads();                          // prev iter's mma done before stage reuse
        if (kc + 2 < NK) issue(kc + 2);
        cp_commit();                              // may be empty (completes immediately)
        cp_wait2();                               // stage kc landed
        __syncthreads();

        const float*  qb = qsm + (kc % 3) * QBUF_F;
        const __half* bb = bsm + (kc % 3) * BBUF_H;

        // overlap: stream the q-copy output half from SMEM (2 of 8 iters per CTA)
        if ((kc >> 1) == (n0 >> 7)) {
            float* o = out + (size_t)m0 * 1024 + DIM + kc * KC;
            #pragma unroll
            for (int j = 0; j < 8; j++) {
                int i = tid + j * 256;
                int r = i >> 4, c = i & 15;
                float4 v = *reinterpret_cast<const float4*>(qb + r * QPITCHF + c * 4);
                *reinterpret_cast<float4*>(o + (size_t)r * 1024 + c * 4) = v;
            }
        }

        #pragma unroll
        for (int ks = 0; ks < 4; ks++) {
            const int k = ks * 16;
            uint32_t a[2][4];
            #pragma unroll
            for (int mf = 0; mf < 2; mf++) {
                const float* base = qb + (wm * 32 + mf * 16 + l4) * QPITCHF + k + 2 * lc;
                float2 v0 = *reinterpret_cast<const float2*>(base);
                float2 v1 = *reinterpret_cast<const float2*>(base + 8 * QPITCHF);
                float2 v2 = *reinterpret_cast<const float2*>(base + 8);
                float2 v3 = *reinterpret_cast<const float2*>(base + 8 * QPITCHF + 8);
                a[mf][0] = packh2(v0.x, v0.y);
                a[mf][1] = packh2(v1.x, v1.y);
                a[mf][2] = packh2(v2.x, v2.y);
                a[mf][3] = packh2(v3.x, v3.y);
            }
            #pragma unroll
            for (int nf = 0; nf < 8; nf++) {
                const __half* brow = bb + (wn * 64 + nf * 8 + l4) * BPITCHH + k + 2 * lc;
                uint32_t b0 = *reinterpret_cast<const uint32_t*>(brow);
                uint32_t b1 = *reinterpret_cast<const uint32_t*>(brow + 8);
                mma16816(d[0][nf], a[0][0], a[0][1], a[0][2], a[0][3], b0, b1);
                mma16816(d[1][nf], a[1][0], a[1][1], a[1][2], a[1][3], b0, b1);
            }
        }
    }

    // epilogue: out[:, n0 + c] = p + pterm
    #pragma unroll
    for (int mf = 0; mf < 2; mf++) {
        #pragma unroll
        for (int rh = 0; rh < 2; rh++) {
            int row = m0 + wm * 32 + mf * 16 + rh * 8 + l4;
            const float* pr = pq + (size_t)row * 1024 + n0 + wn * 64 + 2 * lc;
            float* orow = out + (size_t)row * 1024 + n0 + wn * 64 + 2 * lc;
            #pragma unroll
            for (int nf = 0; nf < 8; nf++) {
                float2 pv = *reinterpret_cast<const float2*>(pr + nf * 8);
                float2 ov;
                ov.x = pv.x + d[mf][nf][rh * 2 + 0];
                ov.y = pv.y + d[mf][nf][rh * 2 + 1];
                *reinterpret_cast<float2*>(orow + nf * 8) = ov;
            }
        }
    }
}

extern "C" void kernel_launch(void* const* d_in, const int* in_sizes, int n_in,
                              void* d_out, int out_size) {
    const float* pq = (const float*)d_in[0];
    const float* A  = (const float*)d_in[1];
    if (n_in >= 2 && in_sizes[0] == DIM * DIM) {   // defensive: swap if order differs
        A  = (const float*)d_in[0];
        pq = (const float*)d_in[1];
    }
    float* out = (float*)d_out;

    cudaFuncSetAttribute(gemm_fused, cudaFuncAttributeMaxDynamicSharedMemorySize, SMEM_BYTES);
    prep_S<<<(DIM * DIM) / 256, 256>>>(A);
    gemm_fused<<<(65536 / TMt) * (DIM / TNt), 256, SMEM_BYTES>>>(pq, out);
}

// round 5
// speedup vs baseline: 1.2799x; 1.2799x over previous
#include <cuda_runtime.h>
#include <cuda_fp16.h>
#include <cstdint>

#define DIM 512
#define TMt 128
#define TNt 128
#define BPITCH 520                          // halves per S row (512 + 8 pad) -> conflict-free
#define SMEM_BYTES (TNt * BPITCH * 2)       // 133120

// S = A + A^T in fp16; 512 KB, L2-resident during GEMM
__device__ __half g_Sh[DIM * DIM];

__global__ void prep_S(const float* __restrict__ A) {
    int i = blockIdx.x * 256 + threadIdx.x;   // 262144 total
    int e = i >> 9, d = i & 511;
    g_Sh[i] = __float2half(A[i] + A[d * DIM + e]);
}

// ---------------- helpers ----------------
__device__ __forceinline__ uint32_t smem_u32(const void* p) {
    return (uint32_t)__cvta_generic_to_shared(p);
}
__device__ __forceinline__ void cpa16(uint32_t dst, const void* src) {
    asm volatile("cp.async.cg.shared.global [%0], [%1], 16;" :: "r"(dst), "l"(src) : "memory");
}
__device__ __forceinline__ uint32_t packh2(float x, float y) {
    __half2 h = __floats2half2_rn(x, y);      // lo = x, hi = y
    return *reinterpret_cast<uint32_t*>(&h);
}
__device__ __forceinline__ void mma16816(float* d, uint32_t a0, uint32_t a1, uint32_t a2,
                                         uint32_t a3, uint32_t b0, uint32_t b1) {
    asm volatile(
        "mma.sync.aligned.m16n8k16.row.col.f32.f16.f16.f32 "
        "{%0,%1,%2,%3}, {%4,%5,%6,%7}, {%8,%9}, {%0,%1,%2,%3};"
        : "+f"(d[0]), "+f"(d[1]), "+f"(d[2]), "+f"(d[3])
        : "r"(a0), "r"(a1), "r"(a2), "r"(a3), "r"(b0), "r"(b1));
}

// ---------------- main fused kernel ----------------
// out[:, 0:512]    = p + q @ S   (pterm[b][e] = sum_d q[b][d] * S[e][d], S symmetric)
// out[:, 512:1024] = q
__global__ void __launch_bounds__(256, 1)
gemm_fused(const float* __restrict__ pq, float* __restrict__ out) {
    extern __shared__ __align__(16) __half bsm[];   // [TNt][BPITCH]
    const uint32_t bsm_u = smem_u32(bsm);

    const int tid = threadIdx.x;
    const int wid = tid >> 5, lane = tid & 31;
    const int wm = wid & 3, wn = wid >> 2;          // warp grid 4(m) x 2(n); warp tile 32x64
    const int l4 = lane >> 2, lc = lane & 3;
    const int bx = blockIdx.x;
    const int m0 = (bx >> 2) * TMt;
    const int n0 = (bx & 3) * TNt;

    // ---- load full B tile (S rows n0..n0+127, all K) once via cp.async
    {
        const __half* ss = g_Sh + (size_t)n0 * DIM;
        #pragma unroll
        for (int j = 0; j < 32; j++) {              // 8192 chunks of 16B
            int c = tid + j * 256;
            int r = c >> 6, k16 = c & 63;           // 64 chunks per 1024B row
            cpa16(bsm_u + (r * BPITCH + k16 * 8) * 2, ss + (size_t)r * DIM + k16 * 8);
        }
        asm volatile("cp.async.commit_group;" ::: "memory");
    }

    // ---- overlap: q-copy output half (this CTA's 128x128 block at cols n0)
    {
        const float* qs = pq + (size_t)m0 * 1024 + DIM + n0;
        float* qo = out + (size_t)m0 * 1024 + DIM + n0;
        #pragma unroll
        for (int j = 0; j < 16; j++) {              // 4096 float4s
            int i = tid + j * 256;
            int r = i >> 5, c = i & 31;
            float4 v = *reinterpret_cast<const float4*>(qs + (size_t)r * 1024 + c * 4);
            *reinterpret_cast<float4*>(qo + (size_t)r * 1024 + c * 4) = v;
        }
    }

    asm volatile("cp.async.wait_group 0;" ::: "memory");
    __syncthreads();                                 // B resident; no more barriers

    // ---- accumulators
    float d[2][8][4];
    #pragma unroll
    for (int i = 0; i < 2; i++)
        #pragma unroll
        for (int j = 0; j < 8; j++)
            #pragma unroll
            for (int k = 0; k < 4; k++) d[i][j][k] = 0.f;

    // A stream base: q rows for this warp
    const float* qA = pq + (size_t)(m0 + wm * 32 + l4) * 1024 + DIM + 2 * lc;
    const __half* bW = bsm + (size_t)(wn * 64 + l4) * BPITCH + 2 * lc;

    // raw A fragments for one k-step: [mf*4 + frag] as float2
    float2 ar[2][8];

    auto load_A = [&](int s, float2 r[8]) {
        const float* base = qA + s * 16;
        #pragma unroll
        for (int mf = 0; mf < 2; mf++) {
            const float* b2 = base + mf * 16 * 1024;
            r[mf * 4 + 0] = *reinterpret_cast<const float2*>(b2);
            r[mf * 4 + 1] = *reinterpret_cast<const float2*>(b2 + 8 * 1024);
            r[mf * 4 + 2] = *reinterpret_cast<const float2*>(b2 + 8);
            r[mf * 4 + 3] = *reinterpret_cast<const float2*>(b2 + 8 * 1024 + 8);
        }
    };

    load_A(0, ar[0]);

    #pragma unroll 4
    for (int s = 0; s < 32; s++) {
        const int cur = s & 1;
        if (s + 1 < 32) load_A(s + 1, ar[cur ^ 1]);

        uint32_t a[2][4];
        #pragma unroll
        for (int j = 0; j < 8; j++)
            a[j >> 2][j & 3] = packh2(ar[cur][j].x, ar[cur][j].y);

        const __half* bk = bW + s * 16;
        #pragma unroll
        for (int nf = 0; nf < 8; nf++) {
            const __half* brow = bk + nf * 8 * BPITCH;
            uint32_t b0 = *reinterpret_cast<const uint32_t*>(brow);
            uint32_t b1 = *reinterpret_cast<const uint32_t*>(brow + 8);
            mma16816(d[0][nf], a[0][0], a[0][1], a[0][2], a[0][3], b0, b1);
            mma16816(d[1][nf], a[1][0], a[1][1], a[1][2], a[1][3], b0, b1);
        }
    }

    // ---- epilogue: out[:, n0 + c] = p + pterm
    #pragma unroll
    for (int mf = 0; mf < 2; mf++) {
        #pragma unroll
        for (int rh = 0; rh < 2; rh++) {
            int row = m0 + wm * 32 + mf * 16 + rh * 8 + l4;
            const float* pr = pq + (size_t)row * 1024 + n0 + wn * 64 + 2 * lc;
            float* orow = out + (size_t)row * 1024 + n0 + wn * 64 + 2 * lc;
            #pragma unroll
            for (int nf = 0; nf < 8; nf++) {
                float2 pv = *reinterpret_cast<const float2*>(pr + nf * 8);
                float2 ov;
                ov.x = pv.x + d[mf][nf][rh * 2 + 0];
                ov.y = pv.y + d[mf][nf][rh * 2 + 1];
                *reinterpret_cast<float2*>(orow + nf * 8) = ov;
            }
        }
    }
}

extern "C" void kernel_launch(void* const* d_in, const int* in_sizes, int n_in,
                              void* d_out, int out_size) {
    const float* pq = (const float*)d_in[0];
    const float* A  = (const float*)d_in[1];
    if (n_in >= 2 && in_sizes[0] == DIM * DIM) {   // defensive: swap if order differs
        A  = (const float*)d_in[0];
        pq = (const float*)d_in[1];
    }
    float* out = (float*)d_out;

    cudaFuncSetAttribute(gemm_fused, cudaFuncAttributeMaxDynamicSharedMemorySize, SMEM_BYTES);
    prep_S<<<(DIM * DIM) / 256, 256>>>(A);
    gemm_fused<<<(65536 / TMt) * (DIM / TNt), 256, SMEM_BYTES>>>(pq, out);
}

// round 6
// speedup vs baseline: 1.8987x; 1.4835x over previous
#include <cuda_runtime.h>
#include <cuda_fp16.h>
#include <cstdint>

#define DIM 512
#define TMt 128
#define TNt 128
#define NKC 8                     // K chunks of 64
#define STAGE_BYTES 16384         // 128 rows x 64 halves x 2B (A or B)
#define SMEM_BYTES (6 * STAGE_BYTES)   // 3 stages x (A+B) = 98304

// fp16 operands prepared once; L2-resident S, streamed qh
__device__ __half g_Sh[DIM * DIM];                 // S = A + A^T   (512 KB)
__device__ __half g_qh[(size_t)65536 * DIM];       // q in fp16     (64 MB)

__global__ void prep_S(const float* __restrict__ A) {
    int i = blockIdx.x * 256 + threadIdx.x;        // 262144
    int e = i >> 9, d = i & 511;
    g_Sh[i] = __float2half(A[i] + A[d * DIM + e]);
}

// reads q (fp32), writes fp16 copy for the GEMM A operand
__global__ void prep_qh(const float* __restrict__ pq) {
    size_t i = (size_t)blockIdx.x * 256 + threadIdx.x;   // 8388608 float4s
    int b = (int)(i >> 7), dc = ((int)i & 127) * 4;
    float4 v = *reinterpret_cast<const float4*>(pq + (size_t)b * 1024 + DIM + dc);
    __half2 h01 = __floats2half2_rn(v.x, v.y);
    __half2 h23 = __floats2half2_rn(v.z, v.w);
    uint2 packed = { *reinterpret_cast<uint32_t*>(&h01), *reinterpret_cast<uint32_t*>(&h23) };
    *reinterpret_cast<uint2*>(g_qh + (size_t)b * DIM + dc) = packed;
}

// ---------------- helpers ----------------
__device__ __forceinline__ uint32_t smem_u32(const void* p) {
    return (uint32_t)__cvta_generic_to_shared(p);
}
__device__ __forceinline__ void cpa16(uint32_t dst, const void* src) {
    asm volatile("cp.async.cg.shared.global [%0], [%1], 16;" :: "r"(dst), "l"(src) : "memory");
}
__device__ __forceinline__ void ldm4(uint32_t* r, uint32_t addr) {
    asm volatile("ldmatrix.sync.aligned.m8n8.x4.shared.b16 {%0,%1,%2,%3}, [%4];"
                 : "=r"(r[0]), "=r"(r[1]), "=r"(r[2]), "=r"(r[3]) : "r"(addr));
}
__device__ __forceinline__ void mma16816(float* d, const uint32_t* a, uint32_t b0, uint32_t b1) {
    asm volatile(
        "mma.sync.aligned.m16n8k16.row.col.f32.f16.f16.f32 "
        "{%0,%1,%2,%3}, {%4,%5,%6,%7}, {%8,%9}, {%0,%1,%2,%3};"
        : "+f"(d[0]), "+f"(d[1]), "+f"(d[2]), "+f"(d[3])
        : "r"(a[0]), "r"(a[1]), "r"(a[2]), "r"(a[3]), "r"(b0), "r"(b1));
}

// ---------------- main fused kernel ----------------
// out[:, 0:512]    = p + q @ S ; out[:, 512:1024] = q (exact fp32 copy)
__global__ void __launch_bounds__(256, 2)
gemm_fused(const float* __restrict__ pq, float* __restrict__ out) {
    extern __shared__ __align__(1024) char smem_raw[];
    const uint32_t sA = smem_u32(smem_raw);                 // 3 A stages
    const uint32_t sB = sA + 3 * STAGE_BYTES;               // 3 B stages

    const int tid = threadIdx.x;
    const int wid = tid >> 5, lane = tid & 31;
    const int wm = wid & 3, wn = wid >> 2;                  // 4(m) x 2(n); warp tile 32x64
    const int l4 = lane >> 2, lc = lane & 3;
    const int bx = blockIdx.x;
    const int m0 = (bx >> 2) * TMt;
    const int n0 = (bx & 3) * TNt;

    // ldmatrix lane-address components (row&7 == lane&7 for all our rows)
    const int sw = lane & 7;                                // swizzle xor
    const int rowA = wm * 32 + (lane & 7) + ((lane >> 3) & 1) * 8;   // + mf*16
    const int hiA = (lane >> 4) & 1;
    const int rowB = wn * 64 + (lane & 7) + ((lane >> 4) & 1) * 8;   // + pair*16
    const int hiB = (lane >> 3) & 1;

    // issue cp.async for K-chunk kc into stage kc%3 (swizzled 128B rows)
    auto issue = [&](int kc) {
        const uint32_t as = sA + (kc % 3) * STAGE_BYTES;
        const uint32_t bs = sB + (kc % 3) * STAGE_BYTES;
        const __half* aq = g_qh + (size_t)m0 * DIM + kc * 64;
        const __half* ss = g_Sh + (size_t)n0 * DIM + kc * 64;
        #pragma unroll
        for (int j = 0; j < 4; j++) {                       // 1024 x 16B each
            int i = tid + j * 256;
            int r = i >> 3, c = i & 7;
            uint32_t off = r * 128 + ((c ^ (r & 7)) << 4);
            cpa16(as + off, aq + (size_t)r * DIM + c * 8);
            cpa16(bs + off, ss + (size_t)r * DIM + c * 8);
        }
        asm volatile("cp.async.commit_group;" ::: "memory");
    };

    issue(0); issue(1); issue(2);

    float d[2][8][4];
    #pragma unroll
    for (int i = 0; i < 2; i++)
        #pragma unroll
        for (int j = 0; j < 8; j++)
            #pragma unroll
            for (int k = 0; k < 4; k++) d[i][j][k] = 0.f;

    for (int kc = 0; kc < NKC; kc++) {
        asm volatile("cp.async.wait_group 2;" ::: "memory");
        __syncthreads();                                    // chunk kc visible to all

        const uint32_t as = sA + (kc % 3) * STAGE_BYTES;
        const uint32_t bs = sB + (kc % 3) * STAGE_BYTES;

        // q-copy slice: 512 float4s per chunk (2 per thread), pure fp32 passthrough
        {
            int i = tid + kc * 512;
            #pragma unroll
            for (int t = 0; t < 2; t++, i += 256) {
                int r = i >> 5, c = i & 31;
                const float* qs = pq + (size_t)(m0 + r) * 1024 + DIM + n0 + c * 4;
                float* qo = out + (size_t)(m0 + r) * 1024 + DIM + n0 + c * 4;
                *reinterpret_cast<float4*>(qo) = *reinterpret_cast<const float4*>(qs);
            }
        }

        #pragma unroll
        for (int s = 0; s < 4; s++) {
            uint32_t a[2][4];
            #pragma unroll
            for (int mf = 0; mf < 2; mf++)
                ldm4(a[mf], as + (rowA + mf * 16) * 128 + (((2 * s + hiA) ^ sw) << 4));
            #pragma unroll
            for (int p = 0; p < 4; p++) {
                uint32_t b[4];
                ldm4(b, bs + (rowB + p * 16) * 128 + (((2 * s + hiB) ^ sw) << 4));
                mma16816(d[0][2 * p + 0], a[0], b[0], b[1]);
                mma16816(d[0][2 * p + 1], a[0], b[2], b[3]);
                mma16816(d[1][2 * p + 0], a[1], b[0], b[1]);
                mma16816(d[1][2 * p + 1], a[1], b[2], b[3]);
            }
        }

        __syncthreads();                                    // all warps done with stage kc%3
        if (kc + 3 < NKC) issue(kc + 3);
        else asm volatile("cp.async.commit_group;" ::: "memory");   // keep group count uniform
    }

    // ---- epilogue: out[:, n0 + c] = p + pterm
    #pragma unroll
    for (int mf = 0; mf < 2; mf++) {
        #pragma unroll
        for (int rh = 0; rh < 2; rh++) {
            int row = m0 + wm * 32 + mf * 16 + rh * 8 + l4;
            const float* pr = pq + (size_t)row * 1024 + n0 + wn * 64 + 2 * lc;
            float* orow = out + (size_t)row * 1024 + n0 + wn * 64 + 2 * lc;
            #pragma unroll
            for (int nf = 0; nf < 8; nf++) {
                float2 pv = *reinterpret_cast<const float2*>(pr + nf * 8);
                float2 ov;
                ov.x = pv.x + d[mf][nf][rh * 2 + 0];
                ov.y = pv.y + d[mf][nf][rh * 2 + 1];
                *reinterpret_cast<float2*>(orow + nf * 8) = ov;
            }
        }
    }
}

extern "C" void kernel_launch(void* const* d_in, const int* in_sizes, int n_in,
                              void* d_out, int out_size) {
    const float* pq = (const float*)d_in[0];
    const float* A  = (const float*)d_in[1];
    if (n_in >= 2 && in_sizes[0] == DIM * DIM) {   // defensive: swap if order differs
        A  = (const float*)d_in[0];
        pq = (const float*)d_in[1];
    }
    float* out = (float*)d_out;

    cudaFuncSetAttribute(gemm_fused, cudaFuncAttributeMaxDynamicSharedMemorySize, SMEM_BYTES);
    prep_S<<<(DIM * DIM) / 256, 256>>>(A);
    prep_qh<<<32768, 256>>>(pq);
    gemm_fused<<<(65536 / TMt) * (DIM / TNt), 256, SMEM_BYTES>>>(pq, out);
}